// round 1
// baseline (speedup 1.0000x reference)
#include <cuda_runtime.h>
#include <cuda_bf16.h>

#define C_DIM 64

// Fused channel-mixing matrix, layout Mt[c][g] (g contiguous) so the apply
// kernel can read (g,g+1) pairs as b64 and (4g..4g+3) as 128-bit LDS.
__device__ __align__(16) float g_Mt[C_DIM * C_DIM];

// ---------------------------------------------------------------------------
// Kernel A: M = Qinv * diag(exp(T * (-2*|S|))) * Q     (tau=0.5, alpha=1)
// grid = 16 blocks x 256 threads, one entry per thread. Q/Qinv staged in smem.
// idx = g*64 + c  -> lanes vary c: Qinv read is broadcast, Q read coalesced.
// ---------------------------------------------------------------------------
__global__ void build_M_kernel(const float* __restrict__ S,
                               const float* __restrict__ Q,
                               const float* __restrict__ Qinv,
                               const int* __restrict__ T) {
    __shared__ float sQ[C_DIM * C_DIM];
    __shared__ float sQi[C_DIM * C_DIM];
    __shared__ float se[C_DIM];
    int tid = threadIdx.x;
    for (int i = tid; i < C_DIM * C_DIM; i += blockDim.x) {
        sQ[i]  = Q[i];
        sQi[i] = Qinv[i];
    }
    if (tid < C_DIM) {
        float t_total = (float)(*T);            // T_PARAM(=1) * T
        float delta   = -2.0f * fabsf(S[tid]);  // -(1/tau)*|S|^alpha
        se[tid] = expf(t_total * delta);
    }
    __syncthreads();

    int idx = blockIdx.x * blockDim.x + tid;    // idx = g*64 + c
    int g = idx >> 6;
    int c = idx & 63;
    float acc = 0.0f;
    #pragma unroll
    for (int f = 0; f < C_DIM; f++)
        acc += sQi[g * C_DIM + f] * se[f] * sQ[f * C_DIM + c];
    g_Mt[c * C_DIM + g] = acc;
}

// ---------------------------------------------------------------------------
// Kernel B: out[:,g,:] = sum_c M[g,c] * x[:,c,:]
// One pixel per thread, 64 fp32 accumulators packed into 32 b64 regs,
// math via fma.rn.f32x2 (2x FFMA rate on sm_103a, PTX-only form).
// M broadcast from shared via 128-bit LDS (conflict-free).
// ---------------------------------------------------------------------------
__global__ __launch_bounds__(256)
void apply_M_kernel(const float* __restrict__ x,
                    float* __restrict__ out,
                    int HW, int Npix) {
    __shared__ __align__(16) unsigned long long sM[C_DIM * 32]; // [c][g-pair]
    int tid = threadIdx.x;
    const unsigned long long* gM = (const unsigned long long*)g_Mt;
    #pragma unroll
    for (int i = 0; i < 8; i++)
        sM[tid + i * 256] = gM[tid + i * 256];
    __syncthreads();

    int q = blockIdx.x * 256 + tid;             // global pixel id (b-major)
    if (q >= Npix) return;
    int b = q / HW;
    int p = q - b * HW;
    size_t base = (size_t)b * C_DIM * HW + p;
    const float* xb = x + base;
    float*       ob = out + base;

    unsigned long long acc[32];
    #pragma unroll
    for (int i = 0; i < 32; i++) acc[i] = 0ULL;  // (0.0f, 0.0f)

    #pragma unroll 1
    for (int c0 = 0; c0 < C_DIM; c0 += 4) {
        // batch 4 strided global loads up front (MLP=4 per warp per iter)
        float xv[4];
        #pragma unroll
        for (int j = 0; j < 4; j++)
            xv[j] = __ldg(xb + (size_t)(c0 + j) * HW);

        #pragma unroll
        for (int j = 0; j < 4; j++) {
            unsigned long long xx;
            unsigned int xu = __float_as_uint(xv[j]);
            asm("mov.b64 %0, {%1, %1};" : "=l"(xx) : "r"(xu));
            const ulonglong2* row = (const ulonglong2*)&sM[(c0 + j) * 32];
            #pragma unroll
            for (int gq = 0; gq < 16; gq++) {
                ulonglong2 m = row[gq];  // 4 M values: g = 4gq .. 4gq+3
                asm("fma.rn.f32x2 %0, %1, %2, %0;"
                    : "+l"(acc[2 * gq])     : "l"(m.x), "l"(xx));
                asm("fma.rn.f32x2 %0, %1, %2, %0;"
                    : "+l"(acc[2 * gq + 1]) : "l"(m.y), "l"(xx));
            }
        }
    }

    #pragma unroll
    for (int gq = 0; gq < 32; gq++) {
        unsigned int lo, hi;
        asm("mov.b64 {%0, %1}, %2;" : "=r"(lo), "=r"(hi) : "l"(acc[gq]));
        ob[(size_t)(2 * gq)     * HW] = __uint_as_float(lo);
        ob[(size_t)(2 * gq + 1) * HW] = __uint_as_float(hi);
    }
}

// ---------------------------------------------------------------------------
// Inputs (metadata order): x [4,64,512,512] f32, S [64] f32, Q [64,64] f32,
// Qinv [64,64] f32, T [] int32. Output: f32, same shape as x.
// ---------------------------------------------------------------------------
extern "C" void kernel_launch(void* const* d_in, const int* in_sizes, int n_in,
                              void* d_out, int out_size) {
    const float* x   = (const float*)d_in[0];
    const float* S   = (const float*)d_in[1];
    const float* Q   = (const float*)d_in[2];
    const float* Qi  = (const float*)d_in[3];
    const int*   T   = (const int*)d_in[4];
    float*       out = (float*)d_out;

    int Npix = in_sizes[0] / C_DIM;   // B*H*W = 1,048,576
    int HW   = Npix / 4;              // B = 4 (problem shape)

    build_M_kernel<<<16, 256>>>(S, Q, Qi, T);
    int grid = (Npix + 255) / 256;
    apply_M_kernel<<<grid, 256>>>(x, out, HW, Npix);
}

// round 2
// speedup vs baseline: 1.7957x; 1.7957x over previous
#include <cuda_runtime.h>

#define C_DIM 64
#define TILE_P 256
#define CHUNK 4
#define NCHUNK (C_DIM / CHUNK)

// Fused channel-mixing matrix, duplicated-pair form: g_M2[c*64+g] = {M[g,c], M[g,c]}
__device__ __align__(16) unsigned long long g_M2[C_DIM * C_DIM];

// ---------------------------------------------------------------------------
// Kernel A: M = Qinv * diag(exp(T * (-2*|S|))) * Q   (tau=0.5, alpha=1, T_PARAM=1)
// ---------------------------------------------------------------------------
__global__ void build_M_kernel(const float* __restrict__ S,
                               const float* __restrict__ Q,
                               const float* __restrict__ Qinv,
                               const int* __restrict__ T) {
    __shared__ float sQ[C_DIM * C_DIM];
    __shared__ float sQi[C_DIM * C_DIM];
    __shared__ float se[C_DIM];
    int tid = threadIdx.x;
    for (int i = tid; i < C_DIM * C_DIM; i += blockDim.x) {
        sQ[i]  = Q[i];
        sQi[i] = Qinv[i];
    }
    if (tid < C_DIM) {
        float t_total = (float)(*T);
        se[tid] = expf(t_total * (-2.0f * fabsf(S[tid])));
    }
    __syncthreads();

    int idx = blockIdx.x * blockDim.x + tid;   // idx = g*64 + c
    int g = idx >> 6;
    int c = idx & 63;
    float acc = 0.0f;
    #pragma unroll
    for (int f = 0; f < C_DIM; f++)
        acc += sQi[g * C_DIM + f] * se[f] * sQ[f * C_DIM + c];
    unsigned long long d;
    unsigned int u = __float_as_uint(acc);
    asm("mov.b64 %0, {%1, %1};" : "=l"(d) : "r"(u));
    g_M2[c * C_DIM + g] = d;
}

// ---------------------------------------------------------------------------
// Kernel B: out[g, pix] = sum_c M[g,c] * x[c, pix], register-blocked GEMM.
// CTA tile: 64 g x 256 pix. Thread tile: 8 g x 8 pix (64 fp32 acc as 32 b64).
// M broadcast from smem (dup pairs), x double-buffered via cp.async.
// ---------------------------------------------------------------------------
#define FMA2(a, m, xv) asm("fma.rn.f32x2 %0, %1, %2, %0;" : "+l"(a) : "l"(m), "l"(xv))

__global__ __launch_bounds__(256, 2)
void apply_M_kernel(const float* __restrict__ x,
                    float* __restrict__ out,
                    int HW) {
    __shared__ __align__(16) unsigned long long sM2[C_DIM * C_DIM];  // 32 KB
    __shared__ __align__(16) float sX[2][CHUNK][TILE_P];             // 8 KB

    int tid = threadIdx.x;

    // Stage M2 (dup pairs) into shared
    {
        const ulonglong2* src = (const ulonglong2*)g_M2;
        ulonglong2* dst = (ulonglong2*)sM2;
        #pragma unroll
        for (int i = 0; i < 8; i++)
            dst[tid + i * 256] = src[tid + i * 256];
    }

    int tiles_per_b = HW / TILE_P;
    int b = blockIdx.x / tiles_per_b;
    int pbase = (blockIdx.x - b * tiles_per_b) * TILE_P;
    const float* xt = x + (size_t)b * C_DIM * HW + pbase;
    float* ot = out + (size_t)b * C_DIM * HW + pbase;

    int tg = tid >> 5;          // 0..7 -> g block
    int tp = tid & 31;          // 0..31 -> pixel lane
    int g0 = tg * 8;

    // cp.async slot: 4 rows x 64 threads x 16B per chunk
    int crow = tid >> 6;                 // 0..3
    int coff = (tid & 63) * 4;           // float offset in row
    unsigned sdst0 = (unsigned)__cvta_generic_to_shared(&sX[0][crow][coff]);
    unsigned sdst1 = (unsigned)__cvta_generic_to_shared(&sX[1][crow][coff]);
    const float* gsrc = xt + (size_t)crow * HW + coff;

    // prologue: chunk 0 -> buf 0
    asm volatile("cp.async.cg.shared.global [%0], [%1], 16;" :: "r"(sdst0), "l"(gsrc));
    asm volatile("cp.async.commit_group;" ::: "memory");

    unsigned long long acc[8][4];
    #pragma unroll
    for (int i = 0; i < 8; i++)
        #pragma unroll
        for (int j = 0; j < 4; j++) acc[i][j] = 0ULL;

    #pragma unroll 1
    for (int k = 0; k < NCHUNK; k++) {
        asm volatile("cp.async.wait_group 0;" ::: "memory");
        __syncthreads();
        if (k + 1 < NCHUNK) {
            const float* g = gsrc + (size_t)(k + 1) * CHUNK * HW;
            unsigned sd = ((k + 1) & 1) ? sdst1 : sdst0;
            asm volatile("cp.async.cg.shared.global [%0], [%1], 16;" :: "r"(sd), "l"(g));
            asm volatile("cp.async.commit_group;" ::: "memory");
        }
        const float* xb = &sX[k & 1][0][0];
        #pragma unroll
        for (int cc = 0; cc < CHUNK; cc++) {
            int c = k * CHUNK + cc;
            const ulonglong2* mrow = (const ulonglong2*)(sM2 + c * C_DIM + g0);
            ulonglong2 m01 = mrow[0];   // g0+0, g0+1
            ulonglong2 m23 = mrow[1];
            ulonglong2 m45 = mrow[2];
            ulonglong2 m67 = mrow[3];
            const ulonglong2* xr = (const ulonglong2*)(xb + cc * TILE_P);
            ulonglong2 xl = xr[tp];        // pixels tp*4 .. tp*4+3
            ulonglong2 xh = xr[32 + tp];   // pixels 128+tp*4 ..

            FMA2(acc[0][0], m01.x, xl.x); FMA2(acc[0][1], m01.x, xl.y);
            FMA2(acc[0][2], m01.x, xh.x); FMA2(acc[0][3], m01.x, xh.y);
            FMA2(acc[1][0], m01.y, xl.x); FMA2(acc[1][1], m01.y, xl.y);
            FMA2(acc[1][2], m01.y, xh.x); FMA2(acc[1][3], m01.y, xh.y);
            FMA2(acc[2][0], m23.x, xl.x); FMA2(acc[2][1], m23.x, xl.y);
            FMA2(acc[2][2], m23.x, xh.x); FMA2(acc[2][3], m23.x, xh.y);
            FMA2(acc[3][0], m23.y, xl.x); FMA2(acc[3][1], m23.y, xl.y);
            FMA2(acc[3][2], m23.y, xh.x); FMA2(acc[3][3], m23.y, xh.y);
            FMA2(acc[4][0], m45.x, xl.x); FMA2(acc[4][1], m45.x, xl.y);
            FMA2(acc[4][2], m45.x, xh.x); FMA2(acc[4][3], m45.x, xh.y);
            FMA2(acc[5][0], m45.y, xl.x); FMA2(acc[5][1], m45.y, xl.y);
            FMA2(acc[5][2], m45.y, xh.x); FMA2(acc[5][3], m45.y, xh.y);
            FMA2(acc[6][0], m67.x, xl.x); FMA2(acc[6][1], m67.x, xl.y);
            FMA2(acc[6][2], m67.x, xh.x); FMA2(acc[6][3], m67.x, xh.y);
            FMA2(acc[7][0], m67.y, xl.x); FMA2(acc[7][1], m67.y, xl.y);
            FMA2(acc[7][2], m67.y, xh.x); FMA2(acc[7][3], m67.y, xh.y);
        }
    }

    // Epilogue: 16 coalesced 16B stores per thread
    #pragma unroll
    for (int i = 0; i < 8; i++) {
        float* orow = ot + (size_t)(g0 + i) * HW;
        ulonglong2 lo, hi;
        lo.x = acc[i][0]; lo.y = acc[i][1];
        hi.x = acc[i][2]; hi.y = acc[i][3];
        *(ulonglong2*)(orow + tp * 4)       = lo;
        *(ulonglong2*)(orow + 128 + tp * 4) = hi;
    }
}

// ---------------------------------------------------------------------------
// Inputs: x [4,64,512,512] f32, S [64] f32, Q [64,64] f32, Qinv [64,64] f32,
// T [] int32. Output: f32 same shape as x.
// ---------------------------------------------------------------------------
extern "C" void kernel_launch(void* const* d_in, const int* in_sizes, int n_in,
                              void* d_out, int out_size) {
    const float* x   = (const float*)d_in[0];
    const float* S   = (const float*)d_in[1];
    const float* Q   = (const float*)d_in[2];
    const float* Qi  = (const float*)d_in[3];
    const int*   T   = (const int*)d_in[4];
    float*       out = (float*)d_out;

    int Npix = in_sizes[0] / C_DIM;   // B*H*W
    int HW   = Npix / 4;              // B = 4

    build_M_kernel<<<16, 256>>>(S, Q, Qi, T);
    int grid = Npix / TILE_P;
    apply_M_kernel<<<grid, 256>>>(x, out, HW);
}

// round 4
// speedup vs baseline: 2.7982x; 1.5583x over previous
#include <cuda_runtime.h>
#include <cuda_bf16.h>
#include <cstdint>

#define C_DIM   64
#define TILE_P  64
#define CHUNK_C 16
#define NCHUNK  4
#define XSTRIDE 68   // floats; pad so B-frag LDS is conflict-free

// Fused channel-mixing matrix M[g][c] (fp32)
__device__ __align__(16) float g_M[C_DIM * C_DIM];

// ---------------------------------------------------------------------------
// Kernel A: M = Qinv * diag(exp(T * (-2*|S|))) * Q   (tau=0.5, alpha=1)
// ---------------------------------------------------------------------------
__global__ void build_M_kernel(const float* __restrict__ S,
                               const float* __restrict__ Q,
                               const float* __restrict__ Qinv,
                               const int* __restrict__ T) {
    __shared__ float sQ[C_DIM * C_DIM];
    __shared__ float sQi[C_DIM * C_DIM];
    __shared__ float se[C_DIM];
    int tid = threadIdx.x;
    for (int i = tid; i < C_DIM * C_DIM; i += blockDim.x) {
        sQ[i]  = Q[i];
        sQi[i] = Qinv[i];
    }
    if (tid < C_DIM) {
        float t_total = (float)(*T);
        se[tid] = expf(t_total * (-2.0f * fabsf(S[tid])));
    }
    __syncthreads();

    int idx = blockIdx.x * blockDim.x + tid;   // idx = g*64 + c
    int g = idx >> 6;
    int c = idx & 63;
    float acc = 0.0f;
    #pragma unroll
    for (int f = 0; f < C_DIM; f++)
        acc += sQi[g * C_DIM + f] * se[f] * sQ[f * C_DIM + c];
    g_M[g * C_DIM + c] = acc;
}

// ---------------------------------------------------------------------------
// bf16 helpers
// ---------------------------------------------------------------------------
__device__ __forceinline__ uint32_t pack_bf16(float lo, float hi) {
    uint32_t r;
    asm("cvt.rn.bf16x2.f32 %0, %1, %2;" : "=r"(r) : "f"(hi), "f"(lo));
    return r;
}
__device__ __forceinline__ float lo_f32(uint32_t p) { return __uint_as_float(p << 16); }
__device__ __forceinline__ float hi_f32(uint32_t p) { return __uint_as_float(p & 0xFFFF0000u); }

#define MMA(d, A, b0, b1)                                                     \
    asm volatile("mma.sync.aligned.m16n8k16.row.col.f32.bf16.bf16.f32 "       \
                 "{%0,%1,%2,%3}, {%4,%5,%6,%7}, {%8,%9}, {%0,%1,%2,%3};"      \
                 : "+f"((d)[0]), "+f"((d)[1]), "+f"((d)[2]), "+f"((d)[3])     \
                 : "r"((A)[0]), "r"((A)[1]), "r"((A)[2]), "r"((A)[3]),        \
                   "r"(b0), "r"(b1))

// ---------------------------------------------------------------------------
// Kernel B: D[64g x Npix] = M x X via mma.sync bf16-split (3 products).
// Warp w owns g rows [16w, 16w+16); M frags in regs; x chunks cp.async'd.
// ---------------------------------------------------------------------------
__global__ __launch_bounds__(128, 4)
void apply_mma_kernel(const float* __restrict__ x,
                      float* __restrict__ out, int HW) {
    __shared__ __align__(16) float sX[2][CHUNK_C][XSTRIDE];

    int tid  = threadIdx.x;
    int wid  = tid >> 5;
    int lane = tid & 31;
    int gid  = lane >> 2;   // 0..7
    int tig  = lane & 3;    // 0..3
    int g0   = wid * 16;

    // ---- A fragments (M hi/lo), loaded once ----
    uint32_t Ahi[NCHUNK][4], Alo[NCHUNK][4];
    {
        int r0 = g0 + gid, r1 = g0 + gid + 8;
        #pragma unroll
        for (int k = 0; k < NCHUNK; k++) {
            int cb = k * CHUNK_C + tig * 2;
            float m[8];
            m[0] = g_M[r0 * 64 + cb];     m[1] = g_M[r0 * 64 + cb + 1];
            m[2] = g_M[r1 * 64 + cb];     m[3] = g_M[r1 * 64 + cb + 1];
            m[4] = g_M[r0 * 64 + cb + 8]; m[5] = g_M[r0 * 64 + cb + 9];
            m[6] = g_M[r1 * 64 + cb + 8]; m[7] = g_M[r1 * 64 + cb + 9];
            #pragma unroll
            for (int j = 0; j < 4; j++) {
                uint32_t h = pack_bf16(m[2 * j], m[2 * j + 1]);
                Ahi[k][j] = h;
                Alo[k][j] = pack_bf16(m[2 * j] - lo_f32(h), m[2 * j + 1] - hi_f32(h));
            }
        }
    }

    // ---- tile coords ----
    int q0 = blockIdx.x * TILE_P;
    int b  = q0 / HW;
    int p0 = q0 - b * HW;
    const float* xb = x   + (size_t)b * C_DIM * HW + p0;
    float*       ob = out + (size_t)b * C_DIM * HW + p0;

    // cp.async fill: 256 16B ops per chunk, 2 per thread
    int f_row0 = tid >> 4;                   // rows 0..7   (op j=0)
    int f_row1 = (tid + 128) >> 4;           // rows 8..15  (op j=1)
    int f_col  = (tid & 15) * 4;             // float offset
    uint32_t sd[2][2];
    #pragma unroll
    for (int bf = 0; bf < 2; bf++) {
        sd[bf][0] = (uint32_t)__cvta_generic_to_shared(&sX[bf][f_row0][f_col]);
        sd[bf][1] = (uint32_t)__cvta_generic_to_shared(&sX[bf][f_row1][f_col]);
    }

    // prologue: chunk 0 -> buf 0
    asm volatile("cp.async.cg.shared.global [%0], [%1], 16;"
                 :: "r"(sd[0][0]), "l"(xb + (size_t)f_row0 * HW + f_col));
    asm volatile("cp.async.cg.shared.global [%0], [%1], 16;"
                 :: "r"(sd[0][1]), "l"(xb + (size_t)f_row1 * HW + f_col));
    asm volatile("cp.async.commit_group;" ::: "memory");

    float d[8][4];
    #pragma unroll
    for (int i = 0; i < 8; i++)
        #pragma unroll
        for (int j = 0; j < 4; j++) d[i][j] = 0.0f;

    #pragma unroll
    for (int k = 0; k < NCHUNK; k++) {
        asm volatile("cp.async.wait_group 0;" ::: "memory");
        __syncthreads();
        if (k + 1 < NCHUNK) {
            const float* gs = xb + (size_t)(k + 1) * CHUNK_C * HW;
            int nb = (k + 1) & 1;
            asm volatile("cp.async.cg.shared.global [%0], [%1], 16;"
                         :: "r"(sd[nb][0]), "l"(gs + (size_t)f_row0 * HW + f_col));
            asm volatile("cp.async.cg.shared.global [%0], [%1], 16;"
                         :: "r"(sd[nb][1]), "l"(gs + (size_t)f_row1 * HW + f_col));
            asm volatile("cp.async.commit_group;" ::: "memory");
        }

        const float* xs = &sX[k & 1][0][0];
        int c2 = tig * 2;
        #pragma unroll
        for (int nt = 0; nt < 8; nt++) {
            int p = nt * 8 + gid;
            float f0 = xs[(c2)     * XSTRIDE + p];
            float f1 = xs[(c2 + 1) * XSTRIDE + p];
            float f2 = xs[(c2 + 8) * XSTRIDE + p];
            float f3 = xs[(c2 + 9) * XSTRIDE + p];
            uint32_t bh0 = pack_bf16(f0, f1);
            uint32_t bh1 = pack_bf16(f2, f3);
            uint32_t bl0 = pack_bf16(f0 - lo_f32(bh0), f1 - hi_f32(bh0));
            uint32_t bl1 = pack_bf16(f2 - lo_f32(bh1), f3 - hi_f32(bh1));
            MMA(d[nt], Ahi[k], bh0, bh1);   // hi*hi
            MMA(d[nt], Alo[k], bh0, bh1);   // lo*hi
            MMA(d[nt], Ahi[k], bl0, bl1);   // hi*lo
        }
    }

    // ---- epilogue: coalesced float2 stores ----
    float* o0 = ob + (size_t)(g0 + gid) * HW;
    float* o1 = ob + (size_t)(g0 + gid + 8) * HW;
    #pragma unroll
    for (int nt = 0; nt < 8; nt++) {
        int p = nt * 8 + tig * 2;
        float2 v0; v0.x = d[nt][0]; v0.y = d[nt][1];
        float2 v1; v1.x = d[nt][2]; v1.y = d[nt][3];
        *(float2*)(o0 + p) = v0;
        *(float2*)(o1 + p) = v1;
    }
}

// ---------------------------------------------------------------------------
// Inputs: x [4,64,512,512] f32, S [64] f32, Q [64,64] f32, Qinv [64,64] f32,
// T [] int32. Output: f32 same shape as x.
// ---------------------------------------------------------------------------
extern "C" void kernel_launch(void* const* d_in, const int* in_sizes, int n_in,
                              void* d_out, int out_size) {
    const float* x   = (const float*)d_in[0];
    const float* S   = (const float*)d_in[1];
    const float* Q   = (const float*)d_in[2];
    const float* Qi  = (const float*)d_in[3];
    const int*   T   = (const int*)d_in[4];
    float*       out = (float*)d_out;

    int Npix = in_sizes[0] / C_DIM;   // B*H*W = 1,048,576
    int HW   = Npix / 4;              // B = 4

    build_M_kernel<<<16, 256>>>(S, Q, Qi, T);
    int grid = Npix / TILE_P;         // 16384
    apply_mma_kernel<<<grid, 128>>>(x, out, HW);
}

// round 5
// speedup vs baseline: 3.3582x; 1.2001x over previous
#include <cuda_runtime.h>
#include <cuda_bf16.h>
#include <cstdint>

#define C_DIM   64
#define TILE_P  128
#define NCHUNK  4
#define QSTRIDE 132   // u64 per kgroup row: 128 pixels + 4 pad (1056B = 32 mod 128)

// M fragments pre-packed in per-lane mma order: index ((wid*4+k)*4+j)*32+lane
__device__ uint32_t g_Ahi[4 * 4 * 4 * 32];
__device__ uint32_t g_Alo[4 * 4 * 4 * 32];

__device__ __forceinline__ uint32_t pack_bf16(float lo, float hi) {
    uint32_t r;
    asm("cvt.rn.bf16x2.f32 %0, %1, %2;" : "=r"(r) : "f"(hi), "f"(lo));
    return r;
}
__device__ __forceinline__ float lo_f32(uint32_t p) { return __uint_as_float(p << 16); }
__device__ __forceinline__ float hi_f32(uint32_t p) { return __uint_as_float(p & 0xFFFF0000u); }

#define MMA(d, A, b0, b1)                                                     \
    asm volatile("mma.sync.aligned.m16n8k16.row.col.f32.bf16.bf16.f32 "       \
                 "{%0,%1,%2,%3}, {%4,%5,%6,%7}, {%8,%9}, {%0,%1,%2,%3};"      \
                 : "+f"((d)[0]), "+f"((d)[1]), "+f"((d)[2]), "+f"((d)[3])     \
                 : "r"((A)[0]), "r"((A)[1]), "r"((A)[2]), "r"((A)[3]),        \
                   "r"(b0), "r"(b1))

#define STS64V(addr, a, b) \
    asm volatile("st.shared.v2.b32 [%0], {%1,%2};" :: "r"(addr), "r"(a), "r"(b) : "memory")
#define LDS64V(a, b, addr) \
    asm volatile("ld.shared.v2.b32 {%0,%1}, [%2];" : "=r"(a), "=r"(b) : "r"(addr))

// ---------------------------------------------------------------------------
// Kernel A: M = Qinv * diag(exp(T*(-2*|S|))) * Q, emitted directly as bf16
// hi/lo mma A-fragments. grid 8 x 256; thread t computes M[g][c], M[g][c+1].
// ---------------------------------------------------------------------------
__global__ void build_M_kernel(const float* __restrict__ S,
                               const float* __restrict__ Q,
                               const float* __restrict__ Qinv,
                               const int* __restrict__ T) {
    __shared__ float sQ[C_DIM * C_DIM];
    __shared__ float sQi[C_DIM * C_DIM];
    __shared__ float se[C_DIM];
    int tid = threadIdx.x;
    for (int i = tid; i < C_DIM * C_DIM; i += blockDim.x) {
        sQ[i]  = Q[i];
        sQi[i] = Qinv[i];
    }
    if (tid < C_DIM) {
        float t_total = (float)(*T);
        se[tid] = expf(t_total * (-2.0f * fabsf(S[tid])));
    }
    __syncthreads();

    int t = blockIdx.x * blockDim.x + tid;   // 0..2047
    int g = t >> 5;
    int c = (t & 31) * 2;
    float a0 = 0.0f, a1 = 0.0f;
    #pragma unroll
    for (int f = 0; f < C_DIM; f++) {
        float w = sQi[g * C_DIM + f] * se[f];
        a0 += w * sQ[f * C_DIM + c];
        a1 += w * sQ[f * C_DIM + c + 1];
    }
    uint32_t h = pack_bf16(a0, a1);
    uint32_t l = pack_bf16(a0 - lo_f32(h), a1 - hi_f32(h));

    // fragment index
    int wid  = g >> 4;
    int gg   = g & 15;
    int gid  = gg & 7;
    int half = gg >> 3;
    int k    = c >> 4;
    int cc   = c & 15;
    int tig  = (cc >> 1) & 3;
    int j    = ((cc >> 3) << 1) + half;
    int lane = gid * 4 + tig;
    int off  = (((wid * 4) + k) * 4 + j) * 32 + lane;
    g_Ahi[off] = h;
    g_Alo[off] = l;
}

// ---------------------------------------------------------------------------
// Kernel B: 256 thr, 128-pixel tile. Warps: (wid&3) = g-quadrant (16 rows),
// (wid>>2) = pixel half (64 px). Per chunk: cooperative bf16 split of x into
// consumer-layout smem fragments, then 8 n-tiles x 3 MMAs per warp.
// ---------------------------------------------------------------------------
__global__ __launch_bounds__(256, 2)
void apply_mma_kernel(const float* __restrict__ x,
                      float* __restrict__ out, int HW) {
    __shared__ __align__(16) unsigned long long sBhi[2][4 * QSTRIDE];
    __shared__ __align__(16) unsigned long long sBlo[2][4 * QSTRIDE];

    int tid   = threadIdx.x;
    int wid   = tid >> 5;
    int lane  = tid & 31;
    int gid   = lane >> 2;
    int tig   = lane & 3;
    int gw    = wid & 3;        // g quadrant
    int phalf = wid >> 2;       // pixel half
    int g0    = gw * 16;

    // ---- A fragments: 32 coalesced loads, pre-packed ----
    uint32_t Ahi[NCHUNK][4], Alo[NCHUNK][4];
    #pragma unroll
    for (int k = 0; k < NCHUNK; k++)
        #pragma unroll
        for (int j = 0; j < 4; j++) {
            int off = ((gw * 4 + k) * 4 + j) * 32 + lane;
            Ahi[k][j] = g_Ahi[off];
            Alo[k][j] = g_Alo[off];
        }

    // ---- tile coords ----
    int q0 = blockIdx.x * TILE_P;
    int b  = q0 / HW;
    int p0 = q0 - b * HW;
    const float* xb = x   + (size_t)b * C_DIM * HW + p0;
    float*       ob = out + (size_t)b * C_DIM * HW + p0;

    // ---- producer mapping: thread -> (kgroups qq,qq+1 ; pixel pp) ----
    int pp = tid & 127;
    int qq = (tid >> 7) * 2;
    const float* pbase0 = xb + (size_t)(qq * 2) * HW + pp;        // q = qq
    const float* pbase1 = xb + (size_t)((qq + 1) * 2) * HW + pp;  // q = qq+1

    uint32_t sts_hi[2], sts_lo[2], lds_hi[2], lds_lo[2];
    #pragma unroll
    for (int bf = 0; bf < 2; bf++) {
        sts_hi[bf] = (uint32_t)__cvta_generic_to_shared(&sBhi[bf][qq * QSTRIDE + pp]);
        sts_lo[bf] = (uint32_t)__cvta_generic_to_shared(&sBlo[bf][qq * QSTRIDE + pp]);
        lds_hi[bf] = (uint32_t)__cvta_generic_to_shared(&sBhi[bf][tig * QSTRIDE + phalf * 64 + gid]);
        lds_lo[bf] = (uint32_t)__cvta_generic_to_shared(&sBlo[bf][tig * QSTRIDE + phalf * 64 + gid]);
    }

    // ---- prefetch chunk 0 ----
    float pf[2][4];
    #pragma unroll
    for (int qi = 0; qi < 2; qi++) {
        const float* pb = qi ? pbase1 : pbase0;
        pf[qi][0] = __ldg(pb);
        pf[qi][1] = __ldg(pb + (size_t)HW);
        pf[qi][2] = __ldg(pb + (size_t)8 * HW);
        pf[qi][3] = __ldg(pb + (size_t)9 * HW);
    }

    float d[8][4];
    #pragma unroll
    for (int i = 0; i < 8; i++)
        #pragma unroll
        for (int j = 0; j < 4; j++) d[i][j] = 0.0f;

    #pragma unroll
    for (int k = 0; k < NCHUNK; k++) {
        int buf = k & 1;
        // split + STS (consumer layout)
        #pragma unroll
        for (int qi = 0; qi < 2; qi++) {
            float f0 = pf[qi][0], f1 = pf[qi][1], f2 = pf[qi][2], f3 = pf[qi][3];
            uint32_t h0 = pack_bf16(f0, f1);
            uint32_t h1 = pack_bf16(f2, f3);
            uint32_t l0 = pack_bf16(f0 - lo_f32(h0), f1 - hi_f32(h0));
            uint32_t l1 = pack_bf16(f2 - lo_f32(h1), f3 - hi_f32(h1));
            STS64V(sts_hi[buf] + qi * (QSTRIDE * 8), h0, h1);
            STS64V(sts_lo[buf] + qi * (QSTRIDE * 8), l0, l1);
        }
        // prefetch next chunk
        if (k + 1 < NCHUNK) {
            size_t co = (size_t)(k + 1) * 16 * HW;
            #pragma unroll
            for (int qi = 0; qi < 2; qi++) {
                const float* pb = (qi ? pbase1 : pbase0) + co;
                pf[qi][0] = __ldg(pb);
                pf[qi][1] = __ldg(pb + (size_t)HW);
                pf[qi][2] = __ldg(pb + (size_t)8 * HW);
                pf[qi][3] = __ldg(pb + (size_t)9 * HW);
            }
        }
        __syncthreads();

        // MMA phase: 8 n-tiles
        #pragma unroll
        for (int nt = 0; nt < 8; nt++) {
            uint32_t bh0, bh1, bl0, bl1;
            LDS64V(bh0, bh1, lds_hi[buf] + nt * 64);
            LDS64V(bl0, bl1, lds_lo[buf] + nt * 64);
            MMA(d[nt], Ahi[k], bh0, bh1);   // hi*hi
            MMA(d[nt], Alo[k], bh0, bh1);   // lo*hi
            MMA(d[nt], Ahi[k], bl0, bl1);   // hi*lo
        }
    }

    // ---- epilogue: coalesced float2 stores ----
    float* o0 = ob + (size_t)(g0 + gid) * HW + phalf * 64;
    float* o1 = ob + (size_t)(g0 + gid + 8) * HW + phalf * 64;
    #pragma unroll
    for (int nt = 0; nt < 8; nt++) {
        int p = nt * 8 + tig * 2;
        float2 v0; v0.x = d[nt][0]; v0.y = d[nt][1];
        float2 v1; v1.x = d[nt][2]; v1.y = d[nt][3];
        *(float2*)(o0 + p) = v0;
        *(float2*)(o1 + p) = v1;
    }
}

// ---------------------------------------------------------------------------
// Inputs: x [4,64,512,512] f32, S [64] f32, Q [64,64] f32, Qinv [64,64] f32,
// T [] int32. Output: f32 same shape as x.
// ---------------------------------------------------------------------------
extern "C" void kernel_launch(void* const* d_in, const int* in_sizes, int n_in,
                              void* d_out, int out_size) {
    const float* x   = (const float*)d_in[0];
    const float* S   = (const float*)d_in[1];
    const float* Q   = (const float*)d_in[2];
    const float* Qi  = (const float*)d_in[3];
    const int*   T   = (const int*)d_in[4];
    float*       out = (float*)d_out;

    int Npix = in_sizes[0] / C_DIM;   // B*H*W = 1,048,576
    int HW   = Npix / 4;              // B = 4

    build_M_kernel<<<8, 256>>>(S, Q, Qi, T);
    int grid = Npix / TILE_P;         // 8192
    apply_mma_kernel<<<grid, 256>>>(x, out, HW);
}

// round 6
// speedup vs baseline: 3.4853x; 1.0379x over previous
#include <cuda_runtime.h>
#include <cuda_bf16.h>
#include <cstdint>

#define C_DIM   64
#define TILE_P  128
#define NCHUNK  4
#define QSTRIDE 132   // u64 per kgroup row: 128 pixels + 4 pad (1056B = 32 mod 128)

// M fragments pre-packed in per-lane mma order: index ((gw*4+k)*4+j)*32+lane
__device__ uint32_t g_Ahi[4 * 4 * 4 * 32];
__device__ uint32_t g_Alo[4 * 4 * 4 * 32];

__device__ __forceinline__ uint32_t pack_bf16(float lo, float hi) {
    uint32_t r;
    asm("cvt.rn.bf16x2.f32 %0, %1, %2;" : "=r"(r) : "f"(hi), "f"(lo));
    return r;
}
__device__ __forceinline__ float lo_f32(uint32_t p) { return __uint_as_float(p << 16); }
__device__ __forceinline__ float hi_f32(uint32_t p) { return __uint_as_float(p & 0xFFFF0000u); }

#define MMA(d, A, b0, b1)                                                     \
    asm volatile("mma.sync.aligned.m16n8k16.row.col.f32.bf16.bf16.f32 "       \
                 "{%0,%1,%2,%3}, {%4,%5,%6,%7}, {%8,%9}, {%0,%1,%2,%3};"      \
                 : "+f"((d)[0]), "+f"((d)[1]), "+f"((d)[2]), "+f"((d)[3])     \
                 : "r"((A)[0]), "r"((A)[1]), "r"((A)[2]), "r"((A)[3]),        \
                   "r"(b0), "r"(b1))

#define STS128V(addr, a, b, c, dd) \
    asm volatile("st.shared.v4.b32 [%0], {%1,%2,%3,%4};" \
                 :: "r"(addr), "r"(a), "r"(b), "r"(c), "r"(dd) : "memory")
#define LDS64V(a, b, addr) \
    asm volatile("ld.shared.v2.b32 {%0,%1}, [%2];" : "=r"(a), "=r"(b) : "r"(addr))

// ---------------------------------------------------------------------------
// Kernel A: M = Qinv * diag(exp(T*(-2*|S|))) * Q, emitted directly as bf16
// hi/lo mma A-fragments. grid 8 x 256; thread t computes M[g][c], M[g][c+1].
// ---------------------------------------------------------------------------
__global__ void build_M_kernel(const float* __restrict__ S,
                               const float* __restrict__ Q,
                               const float* __restrict__ Qinv,
                               const int* __restrict__ T) {
    __shared__ float sQ[C_DIM * C_DIM];
    __shared__ float sQi[C_DIM * C_DIM];
    __shared__ float se[C_DIM];
    int tid = threadIdx.x;
    for (int i = tid; i < C_DIM * C_DIM; i += blockDim.x) {
        sQ[i]  = Q[i];
        sQi[i] = Qinv[i];
    }
    if (tid < C_DIM) {
        float t_total = (float)(*T);
        se[tid] = expf(t_total * (-2.0f * fabsf(S[tid])));
    }
    __syncthreads();

    int t = blockIdx.x * blockDim.x + tid;   // 0..2047
    int g = t >> 5;
    int c = (t & 31) * 2;
    float a0 = 0.0f, a1 = 0.0f;
    #pragma unroll
    for (int f = 0; f < C_DIM; f++) {
        float w = sQi[g * C_DIM + f] * se[f];
        a0 += w * sQ[f * C_DIM + c];
        a1 += w * sQ[f * C_DIM + c + 1];
    }
    uint32_t h = pack_bf16(a0, a1);
    uint32_t l = pack_bf16(a0 - lo_f32(h), a1 - hi_f32(h));

    int wid  = g >> 4;
    int gg   = g & 15;
    int gid  = gg & 7;
    int half = gg >> 3;
    int k    = c >> 4;
    int cc   = c & 15;
    int tig  = (cc >> 1) & 3;
    int j    = ((cc >> 3) << 1) + half;
    int lane = gid * 4 + tig;
    int off  = (((wid * 4) + k) * 4 + j) * 32 + lane;
    g_Ahi[off] = h;
    g_Alo[off] = l;
}

// ---------------------------------------------------------------------------
// Kernel B: 256 thr, 128-pixel tile. Producer: thread = (qq 0..3, 2 pixels),
// 4x LDG.64/chunk, 2-chunk-deep register prefetch, STS.128 frag stores.
// Consumer: warp (gw, phalf) does 8 n-tiles x (2 LDS.64 + 3 MMA) per chunk.
// ---------------------------------------------------------------------------
__global__ __launch_bounds__(256, 2)
void apply_mma_kernel(const float* __restrict__ x,
                      float* __restrict__ out, int HW) {
    __shared__ __align__(16) unsigned long long sBhi[2][4 * QSTRIDE];
    __shared__ __align__(16) unsigned long long sBlo[2][4 * QSTRIDE];

    int tid   = threadIdx.x;
    int wid   = tid >> 5;
    int lane  = tid & 31;
    int gid   = lane >> 2;
    int tig   = lane & 3;
    int gw    = wid & 3;        // g quadrant
    int phalf = wid >> 2;       // pixel half
    int g0    = gw * 16;

    // ---- A fragments: 32 coalesced loads, pre-packed ----
    uint32_t Ahi[NCHUNK][4], Alo[NCHUNK][4];
    #pragma unroll
    for (int k = 0; k < NCHUNK; k++)
        #pragma unroll
        for (int j = 0; j < 4; j++) {
            int off = ((gw * 4 + k) * 4 + j) * 32 + lane;
            Ahi[k][j] = g_Ahi[off];
            Alo[k][j] = g_Alo[off];
        }

    // ---- tile coords ----
    int q0 = blockIdx.x * TILE_P;
    int b  = q0 / HW;
    int p0 = q0 - b * HW;
    const float* xb = x   + (size_t)b * C_DIM * HW + p0;
    float*       ob = out + (size_t)b * C_DIM * HW + p0;

    // ---- producer mapping: thread -> kgroup qq, pixels pp2, pp2+1 ----
    int qq  = tid >> 6;            // 0..3
    int pp2 = (tid & 63) * 2;      // even pixel
    const float2* r0 = (const float2*)(xb + (size_t)(2 * qq)     * HW + pp2);
    const float2* r1 = (const float2*)(xb + (size_t)(2 * qq + 1) * HW + pp2);
    const float2* r2 = (const float2*)(xb + (size_t)(2 * qq + 8) * HW + pp2);
    const float2* r3 = (const float2*)(xb + (size_t)(2 * qq + 9) * HW + pp2);
    size_t cstep = (size_t)16 * HW / 2;   // chunk stride in float2

    uint32_t sts_hi[2], sts_lo[2], lds_hi[2], lds_lo[2];
    #pragma unroll
    for (int bf = 0; bf < 2; bf++) {
        sts_hi[bf] = (uint32_t)__cvta_generic_to_shared(&sBhi[bf][qq * QSTRIDE + pp2]);
        sts_lo[bf] = (uint32_t)__cvta_generic_to_shared(&sBlo[bf][qq * QSTRIDE + pp2]);
        lds_hi[bf] = (uint32_t)__cvta_generic_to_shared(&sBhi[bf][tig * QSTRIDE + phalf * 64 + gid]);
        lds_lo[bf] = (uint32_t)__cvta_generic_to_shared(&sBlo[bf][tig * QSTRIDE + phalf * 64 + gid]);
    }

    // ---- prefetch chunks 0 and 1 (2-deep) ----
    float2 pf[2][4];
    #pragma unroll
    for (int c = 0; c < 2; c++) {
        size_t o = (size_t)c * cstep;
        pf[c][0] = __ldg(r0 + o);
        pf[c][1] = __ldg(r1 + o);
        pf[c][2] = __ldg(r2 + o);
        pf[c][3] = __ldg(r3 + o);
    }

    float d[8][4];
    #pragma unroll
    for (int i = 0; i < 8; i++)
        #pragma unroll
        for (int j = 0; j < 4; j++) d[i][j] = 0.0f;

    #pragma unroll
    for (int k = 0; k < NCHUNK; k++) {
        int buf = k & 1;
        // split + STS.128 (consumer layout); pixel pp2 then pp2+1
        {
            float2 fa = pf[buf][0], fb = pf[buf][1], fc = pf[buf][2], fd = pf[buf][3];
            uint32_t h0  = pack_bf16(fa.x, fb.x);
            uint32_t h1  = pack_bf16(fc.x, fd.x);
            uint32_t h0p = pack_bf16(fa.y, fb.y);
            uint32_t h1p = pack_bf16(fc.y, fd.y);
            uint32_t l0  = pack_bf16(fa.x - lo_f32(h0),  fb.x - hi_f32(h0));
            uint32_t l1  = pack_bf16(fc.x - lo_f32(h1),  fd.x - hi_f32(h1));
            uint32_t l0p = pack_bf16(fa.y - lo_f32(h0p), fb.y - hi_f32(h0p));
            uint32_t l1p = pack_bf16(fc.y - lo_f32(h1p), fd.y - hi_f32(h1p));
            STS128V(sts_hi[buf], h0, h1, h0p, h1p);
            STS128V(sts_lo[buf], l0, l1, l0p, l1p);
        }
        // prefetch chunk k+2 into the slot just consumed
        if (k + 2 < NCHUNK) {
            size_t o = (size_t)(k + 2) * cstep;
            pf[buf][0] = __ldg(r0 + o);
            pf[buf][1] = __ldg(r1 + o);
            pf[buf][2] = __ldg(r2 + o);
            pf[buf][3] = __ldg(r3 + o);
        }
        __syncthreads();

        // MMA phase: 8 n-tiles
        #pragma unroll
        for (int nt = 0; nt < 8; nt++) {
            uint32_t bh0, bh1, bl0, bl1;
            LDS64V(bh0, bh1, lds_hi[buf] + nt * 64);
            LDS64V(bl0, bl1, lds_lo[buf] + nt * 64);
            MMA(d[nt], Ahi[k], bh0, bh1);   // hi*hi
            MMA(d[nt], Alo[k], bh0, bh1);   // lo*hi
            MMA(d[nt], Ahi[k], bl0, bl1);   // hi*lo
        }
    }

    // ---- epilogue: coalesced float2 stores ----
    float* o0 = ob + (size_t)(g0 + gid) * HW + phalf * 64;
    float* o1 = ob + (size_t)(g0 + gid + 8) * HW + phalf * 64;
    #pragma unroll
    for (int nt = 0; nt < 8; nt++) {
        int p = nt * 8 + tig * 2;
        float2 v0; v0.x = d[nt][0]; v0.y = d[nt][1];
        float2 v1; v1.x = d[nt][2]; v1.y = d[nt][3];
        *(float2*)(o0 + p) = v0;
        *(float2*)(o1 + p) = v1;
    }
}

// ---------------------------------------------------------------------------
// Inputs: x [4,64,512,512] f32, S [64] f32, Q [64,64] f32, Qinv [64,64] f32,
// T [] int32. Output: f32 same shape as x.
// ---------------------------------------------------------------------------
extern "C" void kernel_launch(void* const* d_in, const int* in_sizes, int n_in,
                              void* d_out, int out_size) {
    const float* x   = (const float*)d_in[0];
    const float* S   = (const float*)d_in[1];
    const float* Q   = (const float*)d_in[2];
    const float* Qi  = (const float*)d_in[3];
    const int*   T   = (const int*)d_in[4];
    float*       out = (float*)d_out;

    int Npix = in_sizes[0] / C_DIM;   // B*H*W = 1,048,576
    int HW   = Npix / 4;              // B = 4

    build_M_kernel<<<8, 256>>>(S, Q, Qi, T);
    int grid = Npix / TILE_P;         // 8192
    apply_mma_kernel<<<grid, 256>>>(x, out, HW);
}

// round 7
// speedup vs baseline: 3.9647x; 1.1376x over previous
#include <cuda_runtime.h>
#include <cuda_bf16.h>
#include <cstdint>

#define C_DIM   64
#define TILE_P  128
#define TILES   4
#define STRIDE  132                       // floats per c-row (528B): conflict-free
#define BUF_FLOATS (C_DIM * STRIDE)       // 8448 floats = 33792 B per buffer
#define SMEM_BYTES (2 * BUF_FLOATS * 4)   // 67584 B

// M fragments pre-packed in per-lane mma order: index ((gblk*4+k)*4+j)*32+lane
__device__ uint32_t g_Ahi[4 * 4 * 4 * 32];
__device__ uint32_t g_Alo[4 * 4 * 4 * 32];

__device__ __forceinline__ uint32_t pack_bf16(float lo, float hi) {
    uint32_t r;
    asm("cvt.rn.bf16x2.f32 %0, %1, %2;" : "=r"(r) : "f"(hi), "f"(lo));
    return r;
}
__device__ __forceinline__ float lo_f32(uint32_t p) { return __uint_as_float(p << 16); }
__device__ __forceinline__ float hi_f32(uint32_t p) { return __uint_as_float(p & 0xFFFF0000u); }

#define MMA(d, A, b0, b1)                                                     \
    asm volatile("mma.sync.aligned.m16n8k16.row.col.f32.bf16.bf16.f32 "       \
                 "{%0,%1,%2,%3}, {%4,%5,%6,%7}, {%8,%9}, {%0,%1,%2,%3};"      \
                 : "+f"((d)[0]), "+f"((d)[1]), "+f"((d)[2]), "+f"((d)[3])     \
                 : "r"((A)[0]), "r"((A)[1]), "r"((A)[2]), "r"((A)[3]),        \
                   "r"(b0), "r"(b1))

#define CP_ASYNC16(sa, ga) \
    asm volatile("cp.async.cg.shared.global [%0], [%1], 16;" :: "r"(sa), "l"(ga))

// ---------------------------------------------------------------------------
// Kernel A: M = Qinv * diag(exp(T*(-2*|S|))) * Q, emitted directly as bf16
// hi/lo mma A-fragments. grid 8 x 256; thread t computes M[g][c], M[g][c+1].
// ---------------------------------------------------------------------------
__global__ void build_M_kernel(const float* __restrict__ S,
                               const float* __restrict__ Q,
                               const float* __restrict__ Qinv,
                               const int* __restrict__ T) {
    __shared__ float sQ[C_DIM * C_DIM];
    __shared__ float sQi[C_DIM * C_DIM];
    __shared__ float se[C_DIM];
    int tid = threadIdx.x;
    for (int i = tid; i < C_DIM * C_DIM; i += blockDim.x) {
        sQ[i]  = Q[i];
        sQi[i] = Qinv[i];
    }
    if (tid < C_DIM) {
        float t_total = (float)(*T);
        se[tid] = expf(t_total * (-2.0f * fabsf(S[tid])));
    }
    __syncthreads();

    int t = blockIdx.x * blockDim.x + tid;   // 0..2047
    int g = t >> 5;
    int c = (t & 31) * 2;
    float a0 = 0.0f, a1 = 0.0f;
    #pragma unroll
    for (int f = 0; f < C_DIM; f++) {
        float w = sQi[g * C_DIM + f] * se[f];
        a0 += w * sQ[f * C_DIM + c];
        a1 += w * sQ[f * C_DIM + c + 1];
    }
    uint32_t h = pack_bf16(a0, a1);
    uint32_t l = pack_bf16(a0 - lo_f32(h), a1 - hi_f32(h));

    int gblk = g >> 4;
    int gg   = g & 15;
    int gid  = gg & 7;
    int half = gg >> 3;
    int k    = c >> 4;
    int cc   = c & 15;
    int tig  = (cc >> 1) & 3;
    int j    = ((cc >> 3) << 1) + half;
    int lane = gid * 4 + tig;
    int off  = (((gblk * 4) + k) * 4 + j) * 32 + lane;
    g_Ahi[off] = h;
    g_Alo[off] = l;
}

// ---------------------------------------------------------------------------
// Kernel B: 256 thr, 4 tiles of 128 px. Warp = (gpair: 32 g-rows) x
// (pq: 32 pixels). Raw f32 x tiles stream via whole-tile cp.async double
// buffer; consumers read conflict-free LDS.32 and split to bf16 in regs.
// ---------------------------------------------------------------------------
__global__ __launch_bounds__(256, 2)
void apply_mma_kernel(const float* __restrict__ x,
                      float* __restrict__ out, int HW) {
    extern __shared__ __align__(16) float sRaw[];   // 2 x [64][STRIDE]

    int tid   = threadIdx.x;
    int wid   = tid >> 5;
    int lane  = tid & 31;
    int gid   = lane >> 2;
    int tig   = lane & 3;
    int gpair = wid & 1;        // g half (32 rows)
    int pq    = wid >> 1;       // pixel quarter (32 px)

    // ---- A fragments: 2 quadrants x 4 k x 4 j, hi+lo (64 regs) ----
    uint32_t Ahi[2][4][4], Alo[2][4][4];
    #pragma unroll
    for (int q = 0; q < 2; q++)
        #pragma unroll
        for (int k = 0; k < 4; k++)
            #pragma unroll
            for (int j = 0; j < 4; j++) {
                int off = (((gpair * 2 + q) * 4 + k) * 4 + j) * 32 + lane;
                Ahi[q][k][j] = g_Ahi[off];
                Alo[q][k][j] = g_Alo[off];
            }

    // ---- CTA coords: 512 consecutive pixels (never crosses batch) ----
    int Q0 = blockIdx.x * (TILE_P * TILES);
    int b  = Q0 / HW;
    int p0 = Q0 - b * HW;
    const float* xb = x   + (size_t)b * C_DIM * HW + p0;
    float*       ob = out + (size_t)b * C_DIM * HW + p0;

    uint32_t sb = (uint32_t)__cvta_generic_to_shared(sRaw);
    int prow = tid >> 5;            // producer row base 0..7
    int pcol = (tid & 31) * 4;      // float col (16B segment)

    // issue whole tile t into buffer t&1 (8 x 16B per thread, 1 commit)
    #define ISSUE_TILE(t)                                                      \
        do {                                                                   \
            uint32_t sbase = sb + (((t) & 1) * BUF_FLOATS) * 4;                \
            const float* gbase = xb + (t) * TILE_P + pcol;                     \
            _Pragma("unroll")                                                  \
            for (int i = 0; i < 8; i++) {                                      \
                int row = i * 8 + prow;                                        \
                CP_ASYNC16(sbase + (uint32_t)(row * STRIDE + pcol) * 4,        \
                           gbase + (size_t)row * HW);                          \
            }                                                                  \
            asm volatile("cp.async.commit_group;" ::: "memory");               \
        } while (0)

    ISSUE_TILE(0);

    float d[2][4][4];
    #pragma unroll
    for (int q = 0; q < 2; q++)
        #pragma unroll
        for (int nt = 0; nt < 4; nt++)
            #pragma unroll
            for (int j = 0; j < 4; j++) d[q][nt][j] = 0.0f;

    #pragma unroll 1
    for (int t = 0; t < TILES; t++) {
        asm volatile("cp.async.wait_group 0;" ::: "memory");
        __syncthreads();
        if (t + 1 < TILES) ISSUE_TILE(t + 1);

        const float* sf = sRaw + (t & 1) * BUF_FLOATS;
        #pragma unroll
        for (int k = 0; k < 4; k++) {
            #pragma unroll
            for (int nt = 0; nt < 4; nt++) {
                int p  = pq * 32 + nt * 8 + gid;
                int c0 = k * 16 + tig * 2;
                float f0 = sf[(c0)     * STRIDE + p];
                float f1 = sf[(c0 + 1) * STRIDE + p];
                float f2 = sf[(c0 + 8) * STRIDE + p];
                float f3 = sf[(c0 + 9) * STRIDE + p];
                uint32_t h0 = pack_bf16(f0, f1);
                uint32_t h1 = pack_bf16(f2, f3);
                uint32_t l0 = pack_bf16(f0 - lo_f32(h0), f1 - hi_f32(h0));
                uint32_t l1 = pack_bf16(f2 - lo_f32(h1), f3 - hi_f32(h1));
                MMA(d[0][nt], Ahi[0][k], h0, h1);
                MMA(d[0][nt], Alo[0][k], h0, h1);
                MMA(d[0][nt], Ahi[0][k], l0, l1);
                MMA(d[1][nt], Ahi[1][k], h0, h1);
                MMA(d[1][nt], Alo[1][k], h0, h1);
                MMA(d[1][nt], Ahi[1][k], l0, l1);
            }
        }

        // ---- epilogue tile t: coalesced float2 stores, reset acc ----
        #pragma unroll
        for (int q = 0; q < 2; q++) {
            int r0 = gpair * 32 + q * 16 + gid;
            float* o0 = ob + (size_t)r0 * HW + t * TILE_P + pq * 32;
            float* o1 = o0 + (size_t)8 * HW;
            #pragma unroll
            for (int nt = 0; nt < 4; nt++) {
                int p = nt * 8 + tig * 2;
                float2 v0; v0.x = d[q][nt][0]; v0.y = d[q][nt][1];
                float2 v1; v1.x = d[q][nt][2]; v1.y = d[q][nt][3];
                *(float2*)(o0 + p) = v0;
                *(float2*)(o1 + p) = v1;
                d[q][nt][0] = 0.0f; d[q][nt][1] = 0.0f;
                d[q][nt][2] = 0.0f; d[q][nt][3] = 0.0f;
            }
        }
    }
}

// ---------------------------------------------------------------------------
// Inputs: x [4,64,512,512] f32, S [64] f32, Q [64,64] f32, Qinv [64,64] f32,
// T [] int32. Output: f32 same shape as x.
// ---------------------------------------------------------------------------
extern "C" void kernel_launch(void* const* d_in, const int* in_sizes, int n_in,
                              void* d_out, int out_size) {
    const float* x   = (const float*)d_in[0];
    const float* S   = (const float*)d_in[1];
    const float* Q   = (const float*)d_in[2];
    const float* Qi  = (const float*)d_in[3];
    const int*   T   = (const int*)d_in[4];
    float*       out = (float*)d_out;

    int Npix = in_sizes[0] / C_DIM;   // B*H*W = 1,048,576
    int HW   = Npix / 4;              // B = 4

    cudaFuncSetAttribute(apply_mma_kernel,
                         cudaFuncAttributeMaxDynamicSharedMemorySize, SMEM_BYTES);

    build_M_kernel<<<8, 256>>>(S, Q, Qi, T);
    int grid = Npix / (TILE_P * TILES);   // 2048
    apply_mma_kernel<<<grid, 256, SMEM_BYTES>>>(x, out, HW);
}